// round 1
// baseline (speedup 1.0000x reference)
#include <cuda_runtime.h>
#include <cstdint>
#include <math.h>

#define T_STEPS 512
#define BATCH   32
#define EMBED   512
#define HID     1024
#define G4      4096   // 4*HID

#define NB 128         // persistent CTAs (one per SM, <=148 so all resident)
#define NT 256
#define HS 1025        // padded shared row stride for h (odd -> conflict-free scalar loads)

#define OFF_HN ((size_t)BATCH * T_STEPS * HID)          // 16777216
#define OFF_CN (OFF_HN + (size_t)BATCH * HID)           // +32768

// ---- scratch (device globals: no allocation allowed) ----
__device__ float g_xproj[(size_t)T_STEPS * G4 * BATCH]; // 256MB, layout [t][j][b]
__device__ float g_h[2][BATCH * HID];                   // ping-pong h
__device__ unsigned g_count;                             // barrier state (returns to 0 each run)
__device__ volatile unsigned g_gen;

// ---------------------------------------------------------------------------
// Software grid barrier (all NB CTAs resident by construction).
// ---------------------------------------------------------------------------
__device__ __forceinline__ void grid_barrier() {
    __syncthreads();
    if (threadIdx.x == 0) {
        unsigned gen = g_gen;
        __threadfence();
        unsigned prev = atomicAdd(&g_count, 1u);
        if (prev == NB - 1) {
            g_count = 0;
            __threadfence();
            g_gen = gen + 1;
        } else {
            while (g_gen == gen) { __nanosleep(64); }
        }
        __threadfence();
    }
    __syncthreads();
}

// ---------------------------------------------------------------------------
// Kernel 1: x_proj[t][j][b] = sum_e emb[ids[b][t]][e] * Wih[j][e]
// Classic 128x128x8 fp32 SGEMM, 8x8 per thread, embedding gather fused on A.
// ---------------------------------------------------------------------------
__global__ void __launch_bounds__(256, 2) xproj_gemm(
    const int* __restrict__ ids,
    const float* __restrict__ emb,
    const float* __restrict__ Wih)
{
    __shared__ float As[8][132];   // [k][m], padded stride 132 (conflict-free stores)
    __shared__ float Bs[8][132];   // [k][n]

    const int m0  = blockIdx.y * 128;
    const int n0  = blockIdx.x * 128;
    const int tid = threadIdx.x;

    // load-role mapping: each thread owns one (row, half-of-k) float4 per tile
    const int mm = tid >> 1;       // 0..127
    const int qa = tid & 1;        // 0..1  (k-quad)
    const int gm = m0 + mm;
    const int tt = gm >> 5;        // row m = t*32 + b
    const int bb = gm & 31;
    const float* arow = emb + (size_t)ids[bb * T_STEPS + tt] * EMBED;
    const float* brow = Wih + (size_t)(n0 + mm) * EMBED;

    // compute-role mapping: 16x16 thread grid, 8x8 accumulators each
    const int tm = tid >> 4;
    const int tn = tid & 15;

    float acc[8][8];
#pragma unroll
    for (int i = 0; i < 8; i++)
#pragma unroll
        for (int j = 0; j < 8; j++) acc[i][j] = 0.f;

    for (int k0 = 0; k0 < EMBED; k0 += 8) {
        float4 av = *(const float4*)(arow + k0 + qa * 4);
        float4 bv = *(const float4*)(brow + k0 + qa * 4);
        __syncthreads();   // previous tile fully consumed
        As[qa * 4 + 0][mm] = av.x;
        As[qa * 4 + 1][mm] = av.y;
        As[qa * 4 + 2][mm] = av.z;
        As[qa * 4 + 3][mm] = av.w;
        Bs[qa * 4 + 0][mm] = bv.x;
        Bs[qa * 4 + 1][mm] = bv.y;
        Bs[qa * 4 + 2][mm] = bv.z;
        Bs[qa * 4 + 3][mm] = bv.w;
        __syncthreads();

#pragma unroll
        for (int kk = 0; kk < 8; kk++) {
            float4 a0 = *(const float4*)(&As[kk][tm * 8]);
            float4 a1 = *(const float4*)(&As[kk][tm * 8 + 4]);
            float4 b0 = *(const float4*)(&Bs[kk][tn * 8]);
            float4 b1 = *(const float4*)(&Bs[kk][tn * 8 + 4]);
            float a[8] = {a0.x, a0.y, a0.z, a0.w, a1.x, a1.y, a1.z, a1.w};
            float b[8] = {b0.x, b0.y, b0.z, b0.w, b1.x, b1.y, b1.z, b1.w};
#pragma unroll
            for (int i = 0; i < 8; i++)
#pragma unroll
                for (int j = 0; j < 8; j++) acc[i][j] += a[i] * b[j];
        }
    }

    // epilogue: scatter to [t][j][b]
#pragma unroll
    for (int i = 0; i < 8; i++) {
        const int gmi = m0 + tm * 8 + i;
        const int t = gmi >> 5;
        const int b = gmi & 31;
        float* base = g_xproj + (size_t)t * G4 * BATCH + b;
#pragma unroll
        for (int j = 0; j < 8; j++) {
            const int n = n0 + tn * 8 + j;
            base[(size_t)n * BATCH] = acc[i][j];
        }
    }
}

// ---------------------------------------------------------------------------
// Kernel 2: persistent LSTM recurrence.
// CTA b owns n-slice [n0, n0+8) of H for all 32 batches -> 32 gate rows.
//   compute phase: thread (jq 0..7, bq 0..31) -> 4 gate rows x 1 batch
//   finalize phase: thread (fi 0..7, fb 0..31) -> gate fusion + c/h update
// h staged to shared per step with a quad-rotation swizzle:
//   element (b, k=4q+c) stored at col 4q + ((c + (q>>3)) & 3), row stride HS=1025
//   -> conflict-free stores (lanes vary q) AND conflict-free loads (lanes vary b)
// ---------------------------------------------------------------------------
__global__ void __launch_bounds__(NT, 1) lstm_seq(
    const float* __restrict__ h0,
    const float* __restrict__ c0,
    const float* __restrict__ Whh,
    float* __restrict__ out)
{
    extern __shared__ float sm[];
    float* h_s     = sm;             // 32 * 1025 floats
    float* gates_s = sm + 32 * HS;   // 32 * 32 floats

    const int tid = threadIdx.x;
    const int n0  = blockIdx.x * 8;

    // init h ping-pong buffer 0 (each CTA writes its own n-slice for all b)
    {
        const int b = tid >> 3;
        const int i = tid & 7;
        g_h[0][b * HID + n0 + i] = h0[b * HID + n0 + i];
    }

    // compute-role constants
    const int jq = tid >> 5;   // 0..7
    const int bq = tid & 31;
    int jrow[4];
#pragma unroll
    for (int r = 0; r < 4; r++) {
        const int rr = jq * 4 + r;                 // 0..31 within CTA
        jrow[r] = (rr >> 3) * HID + n0 + (rr & 7); // gate*H + n
    }
    const float* Wp0 = Whh + (size_t)jrow[0] * HID;
    const float* Wp1 = Whh + (size_t)jrow[1] * HID;
    const float* Wp2 = Whh + (size_t)jrow[2] * HID;
    const float* Wp3 = Whh + (size_t)jrow[3] * HID;

    // finalize-role constants; c lives in a register for the whole sequence
    const int fi = tid >> 5;   // 0..7
    const int fb = tid & 31;
    const int cidx = fb * HID + n0 + fi;
    float c_reg = c0[cidx];
    float h_reg = 0.f;

    grid_barrier();   // h0 fully materialized in g_h[0]

    for (int t = 0; t < T_STEPS; t++) {
        const float* hread = g_h[t & 1];
        float* hwrite      = g_h[(t & 1) ^ 1];

        // ---- stage h -> shared (coalesced LDG.128, rotated conflict-free STS)
        for (int idx = tid; idx < (BATCH * HID / 4); idx += NT) {
            const int b = idx >> 8;          // 0..31
            const int q = idx & 255;         // k-quad 0..255
            float4 v = __ldcg((const float4*)(hread + b * HID + q * 4));
            const int rot = (q >> 3) & 3;
            float* d = h_s + b * HS + q * 4;
            d[(0 + rot) & 3] = v.x;
            d[(1 + rot) & 3] = v.y;
            d[(2 + rot) & 3] = v.z;
            d[(3 + rot) & 3] = v.w;
        }
        __syncthreads();

        // ---- gates GEMM slice: acc = xproj[t][j][bq] + W_hh[j,:] . h[bq,:]
        const float* xp = g_xproj + (size_t)t * G4 * BATCH + bq;
        float acc0 = xp[(size_t)jrow[0] * BATCH];
        float acc1 = xp[(size_t)jrow[1] * BATCH];
        float acc2 = xp[(size_t)jrow[2] * BATCH];
        float acc3 = xp[(size_t)jrow[3] * BATCH];
        const float* hb = h_s + bq * HS;

#pragma unroll 4
        for (int kb = 0; kb < HID / 32; kb++) {   // 32 blocks of 32 k
            const int rot = kb & 3;               // constant per unrolled copy
            const int kbase = kb * 32;
#pragma unroll
            for (int kc = 0; kc < 32; kc += 4) {
                const int k = kbase + kc;
                const float hv0 = hb[k + ((0 + rot) & 3)];
                const float hv1 = hb[k + ((1 + rot) & 3)];
                const float hv2 = hb[k + ((2 + rot) & 3)];
                const float hv3 = hb[k + ((3 + rot) & 3)];
                const float4 w0 = *(const float4*)(Wp0 + k);
                const float4 w1 = *(const float4*)(Wp1 + k);
                const float4 w2 = *(const float4*)(Wp2 + k);
                const float4 w3 = *(const float4*)(Wp3 + k);
                acc0 += w0.x * hv0; acc0 += w0.y * hv1; acc0 += w0.z * hv2; acc0 += w0.w * hv3;
                acc1 += w1.x * hv0; acc1 += w1.y * hv1; acc1 += w1.z * hv2; acc1 += w1.w * hv3;
                acc2 += w2.x * hv0; acc2 += w2.y * hv1; acc2 += w2.z * hv2; acc2 += w2.w * hv3;
                acc3 += w3.x * hv0; acc3 += w3.y * hv1; acc3 += w3.z * hv2; acc3 += w3.w * hv3;
            }
        }

        gates_s[(jq * 4 + 0) * 32 + bq] = acc0;
        gates_s[(jq * 4 + 1) * 32 + bq] = acc1;
        gates_s[(jq * 4 + 2) * 32 + bq] = acc2;
        gates_s[(jq * 4 + 3) * 32 + bq] = acc3;
        __syncthreads();

        // ---- gate fusion + state update
        const float gi_ = gates_s[( 0 + fi) * 32 + fb];
        const float gf_ = gates_s[( 8 + fi) * 32 + fb];
        const float gg_ = gates_s[(16 + fi) * 32 + fb];
        const float go_ = gates_s[(24 + fi) * 32 + fb];
        const float I = 1.f / (1.f + expf(-gi_));
        const float F = 1.f / (1.f + expf(-gf_));
        const float O = 1.f / (1.f + expf(-go_));
        const float G = tanhf(gg_);
        c_reg = F * c_reg + I * G;
        h_reg = O * tanhf(c_reg);

        hwrite[cidx] = h_reg;
        out[((size_t)fb * T_STEPS + t) * HID + n0 + fi] = h_reg;

        grid_barrier();   // h fully published before next step's staging
    }

    // final states
    out[OFF_HN + cidx] = h_reg;
    out[OFF_CN + cidx] = c_reg;
}

// ---------------------------------------------------------------------------
extern "C" void kernel_launch(void* const* d_in, const int* in_sizes, int n_in,
                              void* d_out, int out_size)
{
    (void)in_sizes; (void)n_in; (void)out_size;
    const int*   ids = (const int*)  d_in[0];
    const float* h0  = (const float*)d_in[1];
    const float* c0  = (const float*)d_in[2];
    const float* emb = (const float*)d_in[3];
    const float* Wih = (const float*)d_in[4];
    const float* Whh = (const float*)d_in[5];
    float* out = (float*)d_out;

    const int smem_bytes = (32 * HS + 32 * 32) * (int)sizeof(float); // 135,296 B
    cudaFuncSetAttribute(lstm_seq, cudaFuncAttributeMaxDynamicSharedMemorySize, smem_bytes);

    dim3 ggrid(G4 / 128, (BATCH * T_STEPS) / 128);  // (32, 128)
    xproj_gemm<<<ggrid, 256>>>(ids, emb, Wih);
    lstm_seq<<<NB, NT, smem_bytes>>>(h0, c0, Whh, out);
}